// round 1
// baseline (speedup 1.0000x reference)
#include <cuda_runtime.h>
#include <cuda_bf16.h>
#include <cstdint>

// Problem constants
#define BB 4
#define TT 2048
#define CC 1024
#define NHH 16
#define HDD 64
#define MM (BB * TT)          // 8192 rows
#define NQKV (3 * CC)         // 3072
#define BH (BB * NHH)         // 64

// Scratch (device globals; allocations are forbidden)
__device__ float g_q[(size_t)BH * TT * HDD];     // [b*16+h][t][d]
__device__ float g_k[(size_t)BH * TT * HDD];
__device__ float g_v[(size_t)BH * TT * HDD];
__device__ float g_ctx[(size_t)MM * CC];         // [b*T+t][c]  (GEMM-ready)

// ---------------------------------------------------------------------------
// SGEMM 128x128x8, 256 threads, 8x8 microtile, double-buffered smem.
// Kernel 1: X[8192,1024] @ Wqkv[1024,3072]  -> scatter into g_q/g_k/g_v
// ---------------------------------------------------------------------------
__global__ __launch_bounds__(256) void qkv_gemm(const float* __restrict__ A,
                                                const float* __restrict__ Bw) {
    const int K = CC, N = NQKV;
    __shared__ float As[2][8][128];
    __shared__ float Bs[2][8][128];

    const int t  = threadIdx.x;
    const int m0 = blockIdx.y * 128;
    const int n0 = blockIdx.x * 128;

    const int arow = t >> 1, acol = (t & 1) * 4;
    const int brow = t >> 5, bcol = (t & 31) * 4;

    // prologue: tile 0 -> buffer 0
    {
        float4 av = *(const float4*)(A + (size_t)(m0 + arow) * K + acol);
        float4 bv = *(const float4*)(Bw + (size_t)brow * N + n0 + bcol);
        As[0][acol + 0][arow] = av.x;
        As[0][acol + 1][arow] = av.y;
        As[0][acol + 2][arow] = av.z;
        As[0][acol + 3][arow] = av.w;
        *(float4*)&Bs[0][brow][bcol] = bv;
    }
    __syncthreads();

    float acc[8][8];
    #pragma unroll
    for (int i = 0; i < 8; i++)
        #pragma unroll
        for (int j = 0; j < 8; j++) acc[i][j] = 0.f;

    const int ty = t >> 4, tx = t & 15;
    const int mo = ty * 8, no = tx * 8;
    const int nk = K / 8;

    for (int kt = 0; kt < nk; kt++) {
        const int cur = kt & 1;
        float4 av2 = make_float4(0, 0, 0, 0), bv2 = make_float4(0, 0, 0, 0);
        if (kt + 1 < nk) {
            const int k0 = (kt + 1) * 8;
            av2 = *(const float4*)(A + (size_t)(m0 + arow) * K + k0 + acol);
            bv2 = *(const float4*)(Bw + (size_t)(k0 + brow) * N + n0 + bcol);
        }
        #pragma unroll
        for (int k = 0; k < 8; k++) {
            float a[8], b[8];
            *(float4*)(a)     = *(const float4*)&As[cur][k][mo];
            *(float4*)(a + 4) = *(const float4*)&As[cur][k][mo + 4];
            *(float4*)(b)     = *(const float4*)&Bs[cur][k][no];
            *(float4*)(b + 4) = *(const float4*)&Bs[cur][k][no + 4];
            #pragma unroll
            for (int i = 0; i < 8; i++)
                #pragma unroll
                for (int j = 0; j < 8; j++) acc[i][j] += a[i] * b[j];
        }
        if (kt + 1 < nk) {
            const int nxt = cur ^ 1;
            As[nxt][acol + 0][arow] = av2.x;
            As[nxt][acol + 1][arow] = av2.y;
            As[nxt][acol + 2][arow] = av2.z;
            As[nxt][acol + 3][arow] = av2.w;
            *(float4*)&Bs[nxt][brow][bcol] = bv2;
            __syncthreads();
        }
    }

    // epilogue: scatter into [b*16+h][t][d] layout
    #pragma unroll
    for (int i = 0; i < 8; i++) {
        const int m  = m0 + mo + i;
        const int b  = m >> 11;          // m / 2048
        const int tq = m & 2047;
        #pragma unroll
        for (int j = 0; j < 8; j++) {
            const int n     = n0 + no + j;
            const int which = n >> 10;   // 0:q 1:k 2:v
            const int cl    = n & 1023;
            const int h     = cl >> 6;
            const int d     = cl & 63;
            float* dst = (which == 0) ? g_q : (which == 1) ? g_k : g_v;
            dst[(((size_t)b * NHH + h) * TT + tq) * HDD + d] = acc[i][j];
        }
    }
}

// ---------------------------------------------------------------------------
// Kernel 3: ctx[8192,1024] @ Wout[1024,1024] + bias -> out
// ---------------------------------------------------------------------------
__global__ __launch_bounds__(256) void out_gemm(const float* __restrict__ Bw,
                                                const float* __restrict__ bias,
                                                float* __restrict__ out) {
    const int K = CC, N = CC;
    const float* A = g_ctx;
    __shared__ float As[2][8][128];
    __shared__ float Bs[2][8][128];

    const int t  = threadIdx.x;
    const int m0 = blockIdx.y * 128;
    const int n0 = blockIdx.x * 128;

    const int arow = t >> 1, acol = (t & 1) * 4;
    const int brow = t >> 5, bcol = (t & 31) * 4;

    {
        float4 av = *(const float4*)(A + (size_t)(m0 + arow) * K + acol);
        float4 bv = *(const float4*)(Bw + (size_t)brow * N + n0 + bcol);
        As[0][acol + 0][arow] = av.x;
        As[0][acol + 1][arow] = av.y;
        As[0][acol + 2][arow] = av.z;
        As[0][acol + 3][arow] = av.w;
        *(float4*)&Bs[0][brow][bcol] = bv;
    }
    __syncthreads();

    float acc[8][8];
    #pragma unroll
    for (int i = 0; i < 8; i++)
        #pragma unroll
        for (int j = 0; j < 8; j++) acc[i][j] = 0.f;

    const int ty = t >> 4, tx = t & 15;
    const int mo = ty * 8, no = tx * 8;
    const int nk = K / 8;

    for (int kt = 0; kt < nk; kt++) {
        const int cur = kt & 1;
        float4 av2 = make_float4(0, 0, 0, 0), bv2 = make_float4(0, 0, 0, 0);
        if (kt + 1 < nk) {
            const int k0 = (kt + 1) * 8;
            av2 = *(const float4*)(A + (size_t)(m0 + arow) * K + k0 + acol);
            bv2 = *(const float4*)(Bw + (size_t)(k0 + brow) * N + n0 + bcol);
        }
        #pragma unroll
        for (int k = 0; k < 8; k++) {
            float a[8], b[8];
            *(float4*)(a)     = *(const float4*)&As[cur][k][mo];
            *(float4*)(a + 4) = *(const float4*)&As[cur][k][mo + 4];
            *(float4*)(b)     = *(const float4*)&Bs[cur][k][no];
            *(float4*)(b + 4) = *(const float4*)&Bs[cur][k][no + 4];
            #pragma unroll
            for (int i = 0; i < 8; i++)
                #pragma unroll
                for (int j = 0; j < 8; j++) acc[i][j] += a[i] * b[j];
        }
        if (kt + 1 < nk) {
            const int nxt = cur ^ 1;
            As[nxt][acol + 0][arow] = av2.x;
            As[nxt][acol + 1][arow] = av2.y;
            As[nxt][acol + 2][arow] = av2.z;
            As[nxt][acol + 3][arow] = av2.w;
            *(float4*)&Bs[nxt][brow][bcol] = bv2;
            __syncthreads();
        }
    }

    #pragma unroll
    for (int i = 0; i < 8; i++) {
        const int m = m0 + mo + i;
        #pragma unroll
        for (int j = 0; j < 8; j += 4) {
            const int n = n0 + no + j;
            float4 o;
            o.x = acc[i][j + 0] + bias[n + 0];
            o.y = acc[i][j + 1] + bias[n + 1];
            o.z = acc[i][j + 2] + bias[n + 2];
            o.w = acc[i][j + 3] + bias[n + 3];
            *(float4*)(out + (size_t)m * N + n) = o;
        }
    }
}

// ---------------------------------------------------------------------------
// Kernel 2: causal flash attention, fp32.
// Block = one (b,h) x 64-query tile, 128 threads.
// Thread (r = tid>>1, half = tid&1) owns S/P[r][half*32..] and O[r][half*32..]
// smem: Qt[d][r], KP (Kt[d][c] reused as Pt[c][r]), Vs[c][j]  == 48 KB exactly
// ---------------------------------------------------------------------------
__global__ __launch_bounds__(128) void flash_attn() {
    __shared__ float Qt[64][64];
    __shared__ float KP[64][64];
    __shared__ float Vs[64][64];

    const int tid = threadIdx.x;
    const int qt  = blockIdx.x;
    const int bh  = blockIdx.y;

    const float* Qp = g_q + (size_t)bh * TT * HDD;
    const float* Kp = g_k + (size_t)bh * TT * HDD;
    const float* Vp = g_v + (size_t)bh * TT * HDD;

    const int r = tid >> 1, half = tid & 1;
    const int qg = qt * 64 + r;

    // Load Q tile transposed: Qt[d][r]
    {
        const int c = tid & 63, hh = tid >> 6;
        const float* qrow = Qp + (size_t)(qt * 64 + c) * HDD;
        #pragma unroll
        for (int f = 0; f < 8; f++) {
            const int d0 = hh * 32 + f * 4;
            float4 v = *(const float4*)(qrow + d0);
            Qt[d0 + 0][c] = v.x;
            Qt[d0 + 1][c] = v.y;
            Qt[d0 + 2][c] = v.z;
            Qt[d0 + 3][c] = v.w;
        }
    }

    float acc[32];
    #pragma unroll
    for (int i = 0; i < 32; i++) acc[i] = 0.f;
    float m_i = -1e30f, l_i = 0.f;

    for (int kt = 0; kt <= qt; kt++) {
        __syncthreads();   // prior iter's PV reads (and Q writes on iter 0) done
        // Load K transposed into KP, V row-major into Vs
        {
            const int c = tid & 63, hh = tid >> 6;
            const float* krow = Kp + (size_t)(kt * 64 + c) * HDD;
            const float* vrow = Vp + (size_t)(kt * 64 + c) * HDD;
            #pragma unroll
            for (int f = 0; f < 8; f++) {
                const int d0 = hh * 32 + f * 4;
                float4 kv = *(const float4*)(krow + d0);
                KP[d0 + 0][c] = kv.x;
                KP[d0 + 1][c] = kv.y;
                KP[d0 + 2][c] = kv.z;
                KP[d0 + 3][c] = kv.w;
                *(float4*)&Vs[c][d0] = *(const float4*)(vrow + d0);
            }
        }
        __syncthreads();

        // S[r][c] = sum_d Q[r][d] * K[c][d], c in [half*32, half*32+32)
        float s[32];
        #pragma unroll
        for (int i = 0; i < 32; i++) s[i] = 0.f;
        for (int d = 0; d < 64; d++) {
            const float qv = Qt[d][r];
            const float4* kc = (const float4*)&KP[d][half * 32];
            #pragma unroll
            for (int i = 0; i < 8; i++) {
                float4 kv = kc[i];
                s[4 * i + 0] += qv * kv.x;
                s[4 * i + 1] += qv * kv.y;
                s[4 * i + 2] += qv * kv.z;
                s[4 * i + 3] += qv * kv.w;
            }
        }
        // scale + causal mask
        const int kbase = kt * 64 + half * 32;
        #pragma unroll
        for (int i = 0; i < 32; i++) {
            s[i] *= 0.125f;                       // 1/sqrt(64)
            if (kbase + i > qg) s[i] = -1e30f;
        }
        // online softmax (pair of threads shares a row; partner is lane^1)
        float mx = -1e30f;
        #pragma unroll
        for (int i = 0; i < 32; i++) mx = fmaxf(mx, s[i]);
        mx = fmaxf(mx, __shfl_xor_sync(0xffffffffu, mx, 1));
        const float m_new = fmaxf(m_i, mx);
        const float alpha = __expf(m_i - m_new);
        float lsum = 0.f;
        #pragma unroll
        for (int i = 0; i < 32; i++) {
            const float p = __expf(s[i] - m_new);
            s[i] = p;
            lsum += p;
        }
        lsum += __shfl_xor_sync(0xffffffffu, lsum, 1);
        l_i = l_i * alpha + lsum;
        m_i = m_new;
        #pragma unroll
        for (int i = 0; i < 32; i++) acc[i] *= alpha;

        __syncthreads();   // everyone done reading KP as Kt
        // Store P transposed: Pt[c][r]
        #pragma unroll
        for (int i = 0; i < 32; i++) KP[half * 32 + i][r] = s[i];
        __syncthreads();

        // O[r][j] += sum_c Pt[c][r] * V[c][j]
        for (int c = 0; c < 64; c++) {
            const float p = KP[c][r];
            const float4* vr = (const float4*)&Vs[c][half * 32];
            #pragma unroll
            for (int i = 0; i < 8; i++) {
                float4 vv = vr[i];
                acc[4 * i + 0] += p * vv.x;
                acc[4 * i + 1] += p * vv.y;
                acc[4 * i + 2] += p * vv.z;
                acc[4 * i + 3] += p * vv.w;
            }
        }
    }

    // finalize: ctx[b*T + t][h*64 + j]
    const float inv = 1.f / l_i;
    const int b = bh >> 4, h = bh & 15;
    float* orow = g_ctx + ((size_t)(b * TT + qg)) * CC + h * HDD + half * 32;
    #pragma unroll
    for (int j = 0; j < 32; j += 4) {
        float4 o;
        o.x = acc[j + 0] * inv;
        o.y = acc[j + 1] * inv;
        o.z = acc[j + 2] * inv;
        o.w = acc[j + 3] * inv;
        *(float4*)(orow + j) = o;
    }
}

// ---------------------------------------------------------------------------
extern "C" void kernel_launch(void* const* d_in, const int* in_sizes, int n_in,
                              void* d_out, int out_size) {
    const float* x     = (const float*)d_in[0];
    const float* w_qkv = (const float*)d_in[1];
    const float* w_out = (const float*)d_in[2];
    const float* b_out = (const float*)d_in[3];
    float* out = (float*)d_out;

    qkv_gemm<<<dim3(NQKV / 128, MM / 128), 256>>>(x, w_qkv);
    flash_attn<<<dim3(TT / 64, BH), 128>>>();
    out_gemm<<<dim3(CC / 128, MM / 128), 256>>>(w_out, b_out, out);
}

// round 2
// speedup vs baseline: 1.9379x; 1.9379x over previous
#include <cuda_runtime.h>
#include <cuda_bf16.h>
#include <cstdint>

// Problem constants
#define BB 4
#define TT 2048
#define CC 1024
#define NHH 16
#define HDD 64
#define MM (BB * TT)          // 8192 rows
#define NQKV (3 * CC)         // 3072
#define BH (BB * NHH)         // 64

// Scratch (device globals; allocations are forbidden)
__device__ float g_q[(size_t)BH * TT * HDD];     // [b*16+h][t][d]
__device__ float g_k[(size_t)BH * TT * HDD];
__device__ float g_v[(size_t)BH * TT * HDD];
__device__ float g_ctx[(size_t)MM * CC];         // [b*T+t][c]  (GEMM-ready)

// ---------------------------------------------------------------------------
// SGEMM 128x128x8, 256 threads, 8x8 microtile, double-buffered smem.
// Kernel 1: X[8192,1024] @ Wqkv[1024,3072]  -> scatter into g_q/g_k/g_v
// ---------------------------------------------------------------------------
__global__ __launch_bounds__(256) void qkv_gemm(const float* __restrict__ A,
                                                const float* __restrict__ Bw) {
    const int K = CC, N = NQKV;
    __shared__ float As[2][8][128];
    __shared__ float Bs[2][8][128];

    const int t  = threadIdx.x;
    const int m0 = blockIdx.y * 128;
    const int n0 = blockIdx.x * 128;

    const int arow = t >> 1, acol = (t & 1) * 4;
    const int brow = t >> 5, bcol = (t & 31) * 4;

    {
        float4 av = *(const float4*)(A + (size_t)(m0 + arow) * K + acol);
        float4 bv = *(const float4*)(Bw + (size_t)brow * N + n0 + bcol);
        As[0][acol + 0][arow] = av.x;
        As[0][acol + 1][arow] = av.y;
        As[0][acol + 2][arow] = av.z;
        As[0][acol + 3][arow] = av.w;
        *(float4*)&Bs[0][brow][bcol] = bv;
    }
    __syncthreads();

    float acc[8][8];
    #pragma unroll
    for (int i = 0; i < 8; i++)
        #pragma unroll
        for (int j = 0; j < 8; j++) acc[i][j] = 0.f;

    const int ty = t >> 4, tx = t & 15;
    const int mo = ty * 8, no = tx * 8;
    const int nk = K / 8;

    for (int kt = 0; kt < nk; kt++) {
        const int cur = kt & 1;
        float4 av2 = make_float4(0, 0, 0, 0), bv2 = make_float4(0, 0, 0, 0);
        if (kt + 1 < nk) {
            const int k0 = (kt + 1) * 8;
            av2 = *(const float4*)(A + (size_t)(m0 + arow) * K + k0 + acol);
            bv2 = *(const float4*)(Bw + (size_t)(k0 + brow) * N + n0 + bcol);
        }
        #pragma unroll
        for (int k = 0; k < 8; k++) {
            float a[8], b[8];
            *(float4*)(a)     = *(const float4*)&As[cur][k][mo];
            *(float4*)(a + 4) = *(const float4*)&As[cur][k][mo + 4];
            *(float4*)(b)     = *(const float4*)&Bs[cur][k][no];
            *(float4*)(b + 4) = *(const float4*)&Bs[cur][k][no + 4];
            #pragma unroll
            for (int i = 0; i < 8; i++)
                #pragma unroll
                for (int j = 0; j < 8; j++) acc[i][j] += a[i] * b[j];
        }
        if (kt + 1 < nk) {
            const int nxt = cur ^ 1;
            As[nxt][acol + 0][arow] = av2.x;
            As[nxt][acol + 1][arow] = av2.y;
            As[nxt][acol + 2][arow] = av2.z;
            As[nxt][acol + 3][arow] = av2.w;
            *(float4*)&Bs[nxt][brow][bcol] = bv2;
            __syncthreads();
        }
    }

    #pragma unroll
    for (int i = 0; i < 8; i++) {
        const int m  = m0 + mo + i;
        const int b  = m >> 11;
        const int tq = m & 2047;
        #pragma unroll
        for (int j = 0; j < 8; j++) {
            const int n     = n0 + no + j;
            const int which = n >> 10;   // 0:q 1:k 2:v
            const int cl    = n & 1023;
            const int h     = cl >> 6;
            const int d     = cl & 63;
            float* dst = (which == 0) ? g_q : (which == 1) ? g_k : g_v;
            dst[(((size_t)b * NHH + h) * TT + tq) * HDD + d] = acc[i][j];
        }
    }
}

// ---------------------------------------------------------------------------
// Kernel 3: ctx[8192,1024] @ Wout[1024,1024] + bias -> out
// ---------------------------------------------------------------------------
__global__ __launch_bounds__(256) void out_gemm(const float* __restrict__ Bw,
                                                const float* __restrict__ bias,
                                                float* __restrict__ out) {
    const int K = CC, N = CC;
    const float* A = g_ctx;
    __shared__ float As[2][8][128];
    __shared__ float Bs[2][8][128];

    const int t  = threadIdx.x;
    const int m0 = blockIdx.y * 128;
    const int n0 = blockIdx.x * 128;

    const int arow = t >> 1, acol = (t & 1) * 4;
    const int brow = t >> 5, bcol = (t & 31) * 4;

    {
        float4 av = *(const float4*)(A + (size_t)(m0 + arow) * K + acol);
        float4 bv = *(const float4*)(Bw + (size_t)brow * N + n0 + bcol);
        As[0][acol + 0][arow] = av.x;
        As[0][acol + 1][arow] = av.y;
        As[0][acol + 2][arow] = av.z;
        As[0][acol + 3][arow] = av.w;
        *(float4*)&Bs[0][brow][bcol] = bv;
    }
    __syncthreads();

    float acc[8][8];
    #pragma unroll
    for (int i = 0; i < 8; i++)
        #pragma unroll
        for (int j = 0; j < 8; j++) acc[i][j] = 0.f;

    const int ty = t >> 4, tx = t & 15;
    const int mo = ty * 8, no = tx * 8;
    const int nk = K / 8;

    for (int kt = 0; kt < nk; kt++) {
        const int cur = kt & 1;
        float4 av2 = make_float4(0, 0, 0, 0), bv2 = make_float4(0, 0, 0, 0);
        if (kt + 1 < nk) {
            const int k0 = (kt + 1) * 8;
            av2 = *(const float4*)(A + (size_t)(m0 + arow) * K + k0 + acol);
            bv2 = *(const float4*)(Bw + (size_t)(k0 + brow) * N + n0 + bcol);
        }
        #pragma unroll
        for (int k = 0; k < 8; k++) {
            float a[8], b[8];
            *(float4*)(a)     = *(const float4*)&As[cur][k][mo];
            *(float4*)(a + 4) = *(const float4*)&As[cur][k][mo + 4];
            *(float4*)(b)     = *(const float4*)&Bs[cur][k][no];
            *(float4*)(b + 4) = *(const float4*)&Bs[cur][k][no + 4];
            #pragma unroll
            for (int i = 0; i < 8; i++)
                #pragma unroll
                for (int j = 0; j < 8; j++) acc[i][j] += a[i] * b[j];
        }
        if (kt + 1 < nk) {
            const int nxt = cur ^ 1;
            As[nxt][acol + 0][arow] = av2.x;
            As[nxt][acol + 1][arow] = av2.y;
            As[nxt][acol + 2][arow] = av2.z;
            As[nxt][acol + 3][arow] = av2.w;
            *(float4*)&Bs[nxt][brow][bcol] = bv2;
            __syncthreads();
        }
    }

    #pragma unroll
    for (int i = 0; i < 8; i++) {
        const int m = m0 + mo + i;
        #pragma unroll
        for (int j = 0; j < 8; j += 4) {
            const int n = n0 + no + j;
            float4 o;
            o.x = acc[i][j + 0] + bias[n + 0];
            o.y = acc[i][j + 1] + bias[n + 1];
            o.z = acc[i][j + 2] + bias[n + 2];
            o.w = acc[i][j + 3] + bias[n + 3];
            *(float4*)(out + (size_t)m * N + n) = o;
        }
    }
}

// ---------------------------------------------------------------------------
// Kernel 2: causal flash attention with tf32 mma.sync.m16n8k8.
// Block = 128 thr (4 warps) x one 64-query tile of one (b,h).
// Warp w owns S/O rows [16w, 16w+16). Key tiles of 64, causal loop.
// K smem region (stride 68) is reused for P after S is consumed.
// ---------------------------------------------------------------------------
#define KSTR 68
#define VSTR 72

__device__ __forceinline__ uint32_t f2tf32(float x) {
    uint32_t u;
    asm("cvt.rna.tf32.f32 %0, %1;" : "=r"(u) : "f"(x));
    return u;
}

__device__ __forceinline__ void mma_tf32(float& d0, float& d1, float& d2, float& d3,
                                         uint32_t a0, uint32_t a1, uint32_t a2, uint32_t a3,
                                         uint32_t b0, uint32_t b1) {
    asm volatile(
        "mma.sync.aligned.m16n8k8.row.col.f32.tf32.tf32.f32 "
        "{%0,%1,%2,%3}, {%4,%5,%6,%7}, {%8,%9}, {%0,%1,%2,%3};\n"
        : "+f"(d0), "+f"(d1), "+f"(d2), "+f"(d3)
        : "r"(a0), "r"(a1), "r"(a2), "r"(a3), "r"(b0), "r"(b1));
}

__global__ __launch_bounds__(128) void flash_attn_mma() {
    __shared__ float KP[64 * KSTR];   // K tile, later reused as P
    __shared__ float Vs[64 * VSTR];

    const int tid  = threadIdx.x;
    const int qt   = blockIdx.x;      // query tile (64 rows)
    const int bh   = blockIdx.y;
    const int w    = tid >> 5;
    const int lane = tid & 31;
    const int g    = lane >> 2;       // 0..7
    const int tg   = lane & 3;        // 0..3

    const float* Qp = g_q + (size_t)bh * TT * HDD;
    const float* Kp = g_k + (size_t)bh * TT * HDD;
    const float* Vp = g_v + (size_t)bh * TT * HDD;

    const int r0 = qt * 64 + w * 16 + g;    // global row of c0/c1
    // Q fragments (softmax scale folded in), tf32
    uint32_t qa[8][4];
    #pragma unroll
    for (int k8 = 0; k8 < 8; k8++) {
        qa[k8][0] = f2tf32(Qp[(size_t)r0 * HDD + k8 * 8 + tg] * 0.125f);
        qa[k8][1] = f2tf32(Qp[(size_t)(r0 + 8) * HDD + k8 * 8 + tg] * 0.125f);
        qa[k8][2] = f2tf32(Qp[(size_t)r0 * HDD + k8 * 8 + tg + 4] * 0.125f);
        qa[k8][3] = f2tf32(Qp[(size_t)(r0 + 8) * HDD + k8 * 8 + tg + 4] * 0.125f);
    }

    float o[8][4];
    #pragma unroll
    for (int n8 = 0; n8 < 8; n8++)
        #pragma unroll
        for (int j = 0; j < 4; j++) o[n8][j] = 0.f;
    float m0 = -1e30f, m1 = -1e30f, l0 = 0.f, l1 = 0.f;

    for (int kt = 0; kt <= qt; kt++) {
        __syncthreads();   // previous iter's P/V reads complete
        // load K (tf32-rounded) and V tiles
        {
            const int row = tid >> 1, seg = (tid & 1) * 32;
            const float* kr = Kp + (size_t)(kt * 64 + row) * HDD + seg;
            const float* vr = Vp + (size_t)(kt * 64 + row) * HDD + seg;
            #pragma unroll
            for (int f = 0; f < 8; f++) {
                float4 kv = *(const float4*)(kr + f * 4);
                float4 vv = *(const float4*)(vr + f * 4);
                float* kd = &KP[row * KSTR + seg + f * 4];
                float* vd = &Vs[row * VSTR + seg + f * 4];
                kd[0] = __uint_as_float(f2tf32(kv.x));
                kd[1] = __uint_as_float(f2tf32(kv.y));
                kd[2] = __uint_as_float(f2tf32(kv.z));
                kd[3] = __uint_as_float(f2tf32(kv.w));
                vd[0] = __uint_as_float(f2tf32(vv.x));
                vd[1] = __uint_as_float(f2tf32(vv.y));
                vd[2] = __uint_as_float(f2tf32(vv.z));
                vd[3] = __uint_as_float(f2tf32(vv.w));
            }
        }
        __syncthreads();

        // S = Q @ K^T  (warp rows x 64 keys)
        float s[8][4];
        #pragma unroll
        for (int n8 = 0; n8 < 8; n8++)
            #pragma unroll
            for (int j = 0; j < 4; j++) s[n8][j] = 0.f;
        #pragma unroll
        for (int n8 = 0; n8 < 8; n8++) {
            #pragma unroll
            for (int k8 = 0; k8 < 8; k8++) {
                uint32_t b0 = __float_as_uint(KP[(n8 * 8 + g) * KSTR + k8 * 8 + tg]);
                uint32_t b1 = __float_as_uint(KP[(n8 * 8 + g) * KSTR + k8 * 8 + tg + 4]);
                mma_tf32(s[n8][0], s[n8][1], s[n8][2], s[n8][3],
                         qa[k8][0], qa[k8][1], qa[k8][2], qa[k8][3], b0, b1);
            }
        }

        // causal mask on the diagonal tile
        if (kt == qt) {
            #pragma unroll
            for (int n8 = 0; n8 < 8; n8++) {
                const int col = kt * 64 + n8 * 8 + tg * 2;
                if (col > r0)          s[n8][0] = -1e30f;
                if (col + 1 > r0)      s[n8][1] = -1e30f;
                if (col > r0 + 8)      s[n8][2] = -1e30f;
                if (col + 1 > r0 + 8)  s[n8][3] = -1e30f;
            }
        }

        // online softmax (rows g and g+8; quad reduction)
        float mx0 = -1e30f, mx1 = -1e30f;
        #pragma unroll
        for (int n8 = 0; n8 < 8; n8++) {
            mx0 = fmaxf(mx0, fmaxf(s[n8][0], s[n8][1]));
            mx1 = fmaxf(mx1, fmaxf(s[n8][2], s[n8][3]));
        }
        mx0 = fmaxf(mx0, __shfl_xor_sync(0xffffffffu, mx0, 1));
        mx0 = fmaxf(mx0, __shfl_xor_sync(0xffffffffu, mx0, 2));
        mx1 = fmaxf(mx1, __shfl_xor_sync(0xffffffffu, mx1, 1));
        mx1 = fmaxf(mx1, __shfl_xor_sync(0xffffffffu, mx1, 2));
        const float nm0 = fmaxf(m0, mx0), nm1 = fmaxf(m1, mx1);
        const float a0 = __expf(m0 - nm0), a1 = __expf(m1 - nm1);
        float ls0 = 0.f, ls1 = 0.f;
        #pragma unroll
        for (int n8 = 0; n8 < 8; n8++) {
            s[n8][0] = __expf(s[n8][0] - nm0);
            s[n8][1] = __expf(s[n8][1] - nm0);
            s[n8][2] = __expf(s[n8][2] - nm1);
            s[n8][3] = __expf(s[n8][3] - nm1);
            ls0 += s[n8][0] + s[n8][1];
            ls1 += s[n8][2] + s[n8][3];
        }
        ls0 += __shfl_xor_sync(0xffffffffu, ls0, 1);
        ls0 += __shfl_xor_sync(0xffffffffu, ls0, 2);
        ls1 += __shfl_xor_sync(0xffffffffu, ls1, 1);
        ls1 += __shfl_xor_sync(0xffffffffu, ls1, 2);
        l0 = l0 * a0 + ls0; l1 = l1 * a1 + ls1;
        m0 = nm0; m1 = nm1;
        #pragma unroll
        for (int n8 = 0; n8 < 8; n8++) {
            o[n8][0] *= a0; o[n8][1] *= a0;
            o[n8][2] *= a1; o[n8][3] *= a1;
        }

        __syncthreads();   // all warps done reading K region
        // store P (tf32) into K region; warp-private 16 rows
        float* Pb = &KP[(w * 16) * KSTR];
        #pragma unroll
        for (int n8 = 0; n8 < 8; n8++) {
            float* p0 = &Pb[g * KSTR + n8 * 8 + tg * 2];
            float* p1 = &Pb[(g + 8) * KSTR + n8 * 8 + tg * 2];
            p0[0] = __uint_as_float(f2tf32(s[n8][0]));
            p0[1] = __uint_as_float(f2tf32(s[n8][1]));
            p1[0] = __uint_as_float(f2tf32(s[n8][2]));
            p1[1] = __uint_as_float(f2tf32(s[n8][3]));
        }
        __syncwarp();

        // O += P @ V
        #pragma unroll
        for (int k8 = 0; k8 < 8; k8++) {
            uint32_t pa0 = __float_as_uint(Pb[g * KSTR + k8 * 8 + tg]);
            uint32_t pa1 = __float_as_uint(Pb[(g + 8) * KSTR + k8 * 8 + tg]);
            uint32_t pa2 = __float_as_uint(Pb[g * KSTR + k8 * 8 + tg + 4]);
            uint32_t pa3 = __float_as_uint(Pb[(g + 8) * KSTR + k8 * 8 + tg + 4]);
            #pragma unroll
            for (int n8 = 0; n8 < 8; n8++) {
                uint32_t b0 = __float_as_uint(Vs[(k8 * 8 + tg) * VSTR + n8 * 8 + g]);
                uint32_t b1 = __float_as_uint(Vs[(k8 * 8 + tg + 4) * VSTR + n8 * 8 + g]);
                mma_tf32(o[n8][0], o[n8][1], o[n8][2], o[n8][3],
                         pa0, pa1, pa2, pa3, b0, b1);
            }
        }
    }

    // epilogue: ctx[b*T + row][h*64 + d]
    const float inv0 = 1.f / l0, inv1 = 1.f / l1;
    const int b = bh >> 4, h = bh & 15;
    float* base0 = g_ctx + ((size_t)(b * TT + r0)) * CC + h * HDD;
    float* base1 = g_ctx + ((size_t)(b * TT + r0 + 8)) * CC + h * HDD;
    #pragma unroll
    for (int n8 = 0; n8 < 8; n8++) {
        const int d = n8 * 8 + tg * 2;
        float2 v0 = make_float2(o[n8][0] * inv0, o[n8][1] * inv0);
        float2 v1 = make_float2(o[n8][2] * inv1, o[n8][3] * inv1);
        *(float2*)(base0 + d) = v0;
        *(float2*)(base1 + d) = v1;
    }
}

// ---------------------------------------------------------------------------
extern "C" void kernel_launch(void* const* d_in, const int* in_sizes, int n_in,
                              void* d_out, int out_size) {
    const float* x     = (const float*)d_in[0];
    const float* w_qkv = (const float*)d_in[1];
    const float* w_out = (const float*)d_in[2];
    const float* b_out = (const float*)d_in[3];
    float* out = (float*)d_out;

    qkv_gemm<<<dim3(NQKV / 128, MM / 128), 256>>>(x, w_qkv);
    flash_attn_mma<<<dim3(TT / 64, BH), 128>>>();
    out_gemm<<<dim3(CC / 128, MM / 128), 256>>>(w_out, b_out, out);
}

// round 4
// speedup vs baseline: 3.3815x; 1.7450x over previous
#include <cuda_runtime.h>
#include <cuda_bf16.h>
#include <cstdint>

// Problem constants
#define BB 4
#define TT 2048
#define CC 1024
#define NHH 16
#define HDD 64
#define MM (BB * TT)          // 8192 rows
#define NQKV (3 * CC)         // 3072
#define BH (BB * NHH)         // 64

// Scratch (device globals; allocations are forbidden)
__device__ float g_q[(size_t)BH * TT * HDD];     // [b*16+h][t][d]
__device__ float g_k[(size_t)BH * TT * HDD];
__device__ float g_v[(size_t)BH * TT * HDD];
__device__ float g_ctx[(size_t)MM * CC];         // [b*T+t][c]  (GEMM-ready)

__device__ __forceinline__ uint32_t f2tf32(float x) {
    uint32_t u;
    asm("cvt.rna.tf32.f32 %0, %1;" : "=r"(u) : "f"(x));
    return u;
}

__device__ __forceinline__ void mma_tf32(float& d0, float& d1, float& d2, float& d3,
                                         uint32_t a0, uint32_t a1, uint32_t a2, uint32_t a3,
                                         uint32_t b0, uint32_t b1) {
    asm volatile(
        "mma.sync.aligned.m16n8k8.row.col.f32.tf32.tf32.f32 "
        "{%0,%1,%2,%3}, {%4,%5,%6,%7}, {%8,%9}, {%0,%1,%2,%3};\n"
        : "+f"(d0), "+f"(d1), "+f"(d2), "+f"(d3)
        : "r"(a0), "r"(a1), "r"(a2), "r"(a3), "r"(b0), "r"(b1));
}

// cvt a float4 to tf32 bit-pattern float4
__device__ __forceinline__ float4 cvt4(float4 v) {
    float4 r;
    r.x = __uint_as_float(f2tf32(v.x));
    r.y = __uint_as_float(f2tf32(v.y));
    r.z = __uint_as_float(f2tf32(v.z));
    r.w = __uint_as_float(f2tf32(v.w));
    return r;
}

// ---------------------------------------------------------------------------
// tf32 GEMM 128x128x16, 256 thr / 8 warps (4m x 2n), warp tile 32x64.
// As[m][k] stride 20 (conflict-free A-frag LDS), Bs[k][n] stride 136.
// Shared mainloop; two kernels differ only in epilogue.
// ---------------------------------------------------------------------------
#define ASTR 20
#define BSTR 136

#define GEMM_MAINLOOP(Aptr, Bptr, Kdim, Ndim)                                   \
    __shared__ float As[2][128][ASTR];                                          \
    __shared__ float Bs[2][16][BSTR];                                           \
    const int t  = threadIdx.x;                                                 \
    const int m0 = blockIdx.y * 128;                                            \
    const int n0 = blockIdx.x * 128;                                            \
    const int ar = t >> 1,  ac = (t & 1) * 8;                                   \
    const int br = t >> 4,  bc = (t & 15) * 8;                                  \
    const int w    = t >> 5;                                                    \
    const int lane = t & 31;                                                    \
    const int g    = lane >> 2, tg = lane & 3;                                  \
    const int mbase = (w >> 1) * 32, nbase = (w & 1) * 64;                      \
    {                                                                           \
        float4 a0v = *(const float4*)(Aptr + (size_t)(m0 + ar) * Kdim + ac);    \
        float4 a1v = *(const float4*)(Aptr + (size_t)(m0 + ar) * Kdim + ac + 4);\
        float4 b0v = *(const float4*)(Bptr + (size_t)br * Ndim + n0 + bc);      \
        float4 b1v = *(const float4*)(Bptr + (size_t)br * Ndim + n0 + bc + 4);  \
        *(float4*)&As[0][ar][ac]     = cvt4(a0v);                               \
        *(float4*)&As[0][ar][ac + 4] = cvt4(a1v);                               \
        *(float4*)&Bs[0][br][bc]     = cvt4(b0v);                               \
        *(float4*)&Bs[0][br][bc + 4] = cvt4(b1v);                               \
    }                                                                           \
    __syncthreads();                                                            \
    float acc[2][8][4];                                                         \
    _Pragma("unroll")                                                           \
    for (int i = 0; i < 2; i++)                                                 \
        _Pragma("unroll")                                                       \
        for (int j = 0; j < 8; j++)                                             \
            _Pragma("unroll")                                                   \
            for (int q = 0; q < 4; q++) acc[i][j][q] = 0.f;                     \
    const int nk = Kdim / 16;                                                   \
    for (int kt = 0; kt < nk; kt++) {                                           \
        const int cur = kt & 1;                                                 \
        float4 pa0, pa1, pb0, pb1;                                              \
        if (kt + 1 < nk) {                                                      \
            const int k0 = (kt + 1) * 16;                                       \
            pa0 = *(const float4*)(Aptr + (size_t)(m0 + ar) * Kdim + k0 + ac);  \
            pa1 = *(const float4*)(Aptr + (size_t)(m0 + ar) * Kdim + k0 + ac + 4); \
            pb0 = *(const float4*)(Bptr + (size_t)(k0 + br) * Ndim + n0 + bc);  \
            pb1 = *(const float4*)(Bptr + (size_t)(k0 + br) * Ndim + n0 + bc + 4); \
        }                                                                       \
        _Pragma("unroll")                                                       \
        for (int k8 = 0; k8 < 2; k8++) {                                        \
            uint32_t af[2][4];                                                  \
            _Pragma("unroll")                                                   \
            for (int mt = 0; mt < 2; mt++) {                                    \
                const int r = mbase + mt * 16 + g;                              \
                af[mt][0] = __float_as_uint(As[cur][r][k8 * 8 + tg]);           \
                af[mt][1] = __float_as_uint(As[cur][r + 8][k8 * 8 + tg]);       \
                af[mt][2] = __float_as_uint(As[cur][r][k8 * 8 + tg + 4]);       \
                af[mt][3] = __float_as_uint(As[cur][r + 8][k8 * 8 + tg + 4]);   \
            }                                                                   \
            uint32_t bf[8][2];                                                  \
            _Pragma("unroll")                                                   \
            for (int nt = 0; nt < 8; nt++) {                                    \
                const int c = nbase + nt * 8 + g;                               \
                bf[nt][0] = __float_as_uint(Bs[cur][k8 * 8 + tg][c]);           \
                bf[nt][1] = __float_as_uint(Bs[cur][k8 * 8 + tg + 4][c]);       \
            }                                                                   \
            _Pragma("unroll")                                                   \
            for (int mt = 0; mt < 2; mt++)                                      \
                _Pragma("unroll")                                               \
                for (int nt = 0; nt < 8; nt++)                                  \
                    mma_tf32(acc[mt][nt][0], acc[mt][nt][1],                    \
                             acc[mt][nt][2], acc[mt][nt][3],                    \
                             af[mt][0], af[mt][1], af[mt][2], af[mt][3],        \
                             bf[nt][0], bf[nt][1]);                             \
        }                                                                       \
        if (kt + 1 < nk) {                                                      \
            const int nxt = cur ^ 1;                                            \
            *(float4*)&As[nxt][ar][ac]     = cvt4(pa0);                         \
            *(float4*)&As[nxt][ar][ac + 4] = cvt4(pa1);                         \
            *(float4*)&Bs[nxt][br][bc]     = cvt4(pb0);                         \
            *(float4*)&Bs[nxt][br][bc + 4] = cvt4(pb1);                         \
            __syncthreads();                                                    \
        }                                                                       \
    }

// Kernel 1: X[8192,1024] @ Wqkv[1024,3072] -> scatter into g_q/g_k/g_v
__global__ __launch_bounds__(256) void qkv_gemm_tf32(const float* __restrict__ A,
                                                     const float* __restrict__ Bw) {
    GEMM_MAINLOOP(A, Bw, CC, NQKV)

    #pragma unroll
    for (int mt = 0; mt < 2; mt++) {
        const int r  = m0 + mbase + mt * 16 + g;
        const int b  = r >> 11;
        const int tq = r & 2047;
        #pragma unroll
        for (int nt = 0; nt < 8; nt++) {
            const int n     = n0 + nbase + nt * 8 + tg * 2;
            const int which = n >> 10;   // 0:q 1:k 2:v
            const int cl    = n & 1023;
            const int h     = cl >> 6;
            const int d     = cl & 63;
            float* dst = (which == 0) ? g_q : (which == 1) ? g_k : g_v;
            float* p0 = dst + (((size_t)b * NHH + h) * TT + tq) * HDD + d;
            *(float2*)p0 = make_float2(acc[mt][nt][0], acc[mt][nt][1]);
            *(float2*)(p0 + 8 * HDD) = make_float2(acc[mt][nt][2], acc[mt][nt][3]);
        }
    }
}

// Kernel 3: ctx[8192,1024] @ Wout[1024,1024] + bias -> out
__global__ __launch_bounds__(256) void out_gemm_tf32(const float* __restrict__ Bw,
                                                     const float* __restrict__ bias,
                                                     float* __restrict__ out) {
    const float* Actx = g_ctx;
    GEMM_MAINLOOP(Actx, Bw, CC, CC)

    #pragma unroll
    for (int mt = 0; mt < 2; mt++) {
        const int r = m0 + mbase + mt * 16 + g;
        #pragma unroll
        for (int nt = 0; nt < 8; nt++) {
            const int n = n0 + nbase + nt * 8 + tg * 2;
            const float bx = bias[n], by = bias[n + 1];
            *(float2*)(out + (size_t)r * CC + n) =
                make_float2(acc[mt][nt][0] + bx, acc[mt][nt][1] + by);
            *(float2*)(out + (size_t)(r + 8) * CC + n) =
                make_float2(acc[mt][nt][2] + bx, acc[mt][nt][3] + by);
        }
    }
}

// ---------------------------------------------------------------------------
// Kernel 2: causal flash attention with tf32 mma.sync.m16n8k8. (unchanged)
// ---------------------------------------------------------------------------
#define KSTR 68
#define VSTR 72

__global__ __launch_bounds__(128) void flash_attn_mma() {
    __shared__ float KP[64 * KSTR];   // K tile, later reused as P
    __shared__ float Vs[64 * VSTR];

    const int tid  = threadIdx.x;
    const int qt   = blockIdx.x;      // query tile (64 rows)
    const int bh   = blockIdx.y;
    const int w    = tid >> 5;
    const int lane = tid & 31;
    const int g    = lane >> 2;       // 0..7
    const int tg   = lane & 3;        // 0..3

    const float* Qp = g_q + (size_t)bh * TT * HDD;
    const float* Kp = g_k + (size_t)bh * TT * HDD;
    const float* Vp = g_v + (size_t)bh * TT * HDD;

    const int r0 = qt * 64 + w * 16 + g;    // global row of c0/c1
    uint32_t qa[8][4];
    #pragma unroll
    for (int k8 = 0; k8 < 8; k8++) {
        qa[k8][0] = f2tf32(Qp[(size_t)r0 * HDD + k8 * 8 + tg] * 0.125f);
        qa[k8][1] = f2tf32(Qp[(size_t)(r0 + 8) * HDD + k8 * 8 + tg] * 0.125f);
        qa[k8][2] = f2tf32(Qp[(size_t)r0 * HDD + k8 * 8 + tg + 4] * 0.125f);
        qa[k8][3] = f2tf32(Qp[(size_t)(r0 + 8) * HDD + k8 * 8 + tg + 4] * 0.125f);
    }

    float o[8][4];
    #pragma unroll
    for (int n8 = 0; n8 < 8; n8++)
        #pragma unroll
        for (int j = 0; j < 4; j++) o[n8][j] = 0.f;
    float m0 = -1e30f, m1 = -1e30f, l0 = 0.f, l1 = 0.f;

    for (int kt = 0; kt <= qt; kt++) {
        __syncthreads();
        {
            const int row = tid >> 1, seg = (tid & 1) * 32;
            const float* kr = Kp + (size_t)(kt * 64 + row) * HDD + seg;
            const float* vr = Vp + (size_t)(kt * 64 + row) * HDD + seg;
            #pragma unroll
            for (int f = 0; f < 8; f++) {
                float4 kv = *(const float4*)(kr + f * 4);
                float4 vv = *(const float4*)(vr + f * 4);
                *(float4*)&KP[row * KSTR + seg + f * 4] = cvt4(kv);
                *(float4*)&Vs[row * VSTR + seg + f * 4] = cvt4(vv);
            }
        }
        __syncthreads();

        float s[8][4];
        #pragma unroll
        for (int n8 = 0; n8 < 8; n8++)
            #pragma unroll
            for (int j = 0; j < 4; j++) s[n8][j] = 0.f;
        #pragma unroll
        for (int n8 = 0; n8 < 8; n8++) {
            #pragma unroll
            for (int k8 = 0; k8 < 8; k8++) {
                uint32_t b0 = __float_as_uint(KP[(n8 * 8 + g) * KSTR + k8 * 8 + tg]);
                uint32_t b1 = __float_as_uint(KP[(n8 * 8 + g) * KSTR + k8 * 8 + tg + 4]);
                mma_tf32(s[n8][0], s[n8][1], s[n8][2], s[n8][3],
                         qa[k8][0], qa[k8][1], qa[k8][2], qa[k8][3], b0, b1);
            }
        }

        if (kt == qt) {
            #pragma unroll
            for (int n8 = 0; n8 < 8; n8++) {
                const int col = kt * 64 + n8 * 8 + tg * 2;
                if (col > r0)          s[n8][0] = -1e30f;
                if (col + 1 > r0)      s[n8][1] = -1e30f;
                if (col > r0 + 8)      s[n8][2] = -1e30f;
                if (col + 1 > r0 + 8)  s[n8][3] = -1e30f;
            }
        }

        float mx0 = -1e30f, mx1 = -1e30f;
        #pragma unroll
        for (int n8 = 0; n8 < 8; n8++) {
            mx0 = fmaxf(mx0, fmaxf(s[n8][0], s[n8][1]));
            mx1 = fmaxf(mx1, fmaxf(s[n8][2], s[n8][3]));
        }
        mx0 = fmaxf(mx0, __shfl_xor_sync(0xffffffffu, mx0, 1));
        mx0 = fmaxf(mx0, __shfl_xor_sync(0xffffffffu, mx0, 2));
        mx1 = fmaxf(mx1, __shfl_xor_sync(0xffffffffu, mx1, 1));
        mx1 = fmaxf(mx1, __shfl_xor_sync(0xffffffffu, mx1, 2));
        const float nm0 = fmaxf(m0, mx0), nm1 = fmaxf(m1, mx1);
        const float a0 = __expf(m0 - nm0), a1 = __expf(m1 - nm1);
        float ls0 = 0.f, ls1 = 0.f;
        #pragma unroll
        for (int n8 = 0; n8 < 8; n8++) {
            s[n8][0] = __expf(s[n8][0] - nm0);
            s[n8][1] = __expf(s[n8][1] - nm0);
            s[n8][2] = __expf(s[n8][2] - nm1);
            s[n8][3] = __expf(s[n8][3] - nm1);
            ls0 += s[n8][0] + s[n8][1];
            ls1 += s[n8][2] + s[n8][3];
        }
        ls0 += __shfl_xor_sync(0xffffffffu, ls0, 1);
        ls0 += __shfl_xor_sync(0xffffffffu, ls0, 2);
        ls1 += __shfl_xor_sync(0xffffffffu, ls1, 1);
        ls1 += __shfl_xor_sync(0xffffffffu, ls1, 2);
        l0 = l0 * a0 + ls0; l1 = l1 * a1 + ls1;
        m0 = nm0; m1 = nm1;
        #pragma unroll
        for (int n8 = 0; n8 < 8; n8++) {
            o[n8][0] *= a0; o[n8][1] *= a0;
            o[n8][2] *= a1; o[n8][3] *= a1;
        }

        __syncthreads();
        float* Pb = &KP[(w * 16) * KSTR];
        #pragma unroll
        for (int n8 = 0; n8 < 8; n8++) {
            float* p0 = &Pb[g * KSTR + n8 * 8 + tg * 2];
            float* p1 = &Pb[(g + 8) * KSTR + n8 * 8 + tg * 2];
            p0[0] = __uint_as_float(f2tf32(s[n8][0]));
            p0[1] = __uint_as_float(f2tf32(s[n8][1]));
            p1[0] = __uint_as_float(f2tf32(s[n8][2]));
            p1[1] = __uint_as_float(f2tf32(s[n8][3]));
        }
        __syncwarp();

        #pragma unroll
        for (int k8 = 0; k8 < 8; k8++) {
            uint32_t pa0 = __float_as_uint(Pb[g * KSTR + k8 * 8 + tg]);
            uint32_t pa1 = __float_as_uint(Pb[(g + 8) * KSTR + k8 * 8 + tg]);
            uint32_t pa2 = __float_as_uint(Pb[g * KSTR + k8 * 8 + tg + 4]);
            uint32_t pa3 = __float_as_uint(Pb[(g + 8) * KSTR + k8 * 8 + tg + 4]);
            #pragma unroll
            for (int n8 = 0; n8 < 8; n8++) {
                uint32_t b0 = __float_as_uint(Vs[(k8 * 8 + tg) * VSTR + n8 * 8 + g]);
                uint32_t b1 = __float_as_uint(Vs[(k8 * 8 + tg + 4) * VSTR + n8 * 8 + g]);
                mma_tf32(o[n8][0], o[n8][1], o[n8][2], o[n8][3],
                         pa0, pa1, pa2, pa3, b0, b1);
            }
        }
    }

    const float inv0 = 1.f / l0, inv1 = 1.f / l1;
    const int b = bh >> 4, h = bh & 15;
    float* base0 = g_ctx + ((size_t)(b * TT + r0)) * CC + h * HDD;
    float* base1 = g_ctx + ((size_t)(b * TT + r0 + 8)) * CC + h * HDD;
    #pragma unroll
    for (int n8 = 0; n8 < 8; n8++) {
        const int d = n8 * 8 + tg * 2;
        *(float2*)(base0 + d) = make_float2(o[n8][0] * inv0, o[n8][1] * inv0);
        *(float2*)(base1 + d) = make_float2(o[n8][2] * inv1, o[n8][3] * inv1);
    }
}

// ---------------------------------------------------------------------------
extern "C" void kernel_launch(void* const* d_in, const int* in_sizes, int n_in,
                              void* d_out, int out_size) {
    const float* x     = (const float*)d_in[0];
    const float* w_qkv = (const float*)d_in[1];
    const float* w_out = (const float*)d_in[2];
    const float* b_out = (const float*)d_in[3];
    float* out = (float*)d_out;

    qkv_gemm_tf32<<<dim3(NQKV / 128, MM / 128), 256>>>(x, w_qkv);
    flash_attn_mma<<<dim3(TT / 64, BH), 128>>>();
    out_gemm_tf32<<<dim3(CC / 128, MM / 128), 256>>>(w_out, b_out, out);
}